// round 6
// baseline (speedup 1.0000x reference)
#include <cuda_runtime.h>
#include <cuda_bf16.h>
#include <float.h>
#include <stdint.h>

// Problem constants
#define BQ     64        // queries
#define HID    768       // hidden
#define KTOP   5
#define TILE_N 128       // evidence rows per block
#define KC     32        // K-chunk
#define NCHUNK (HID / KC)
#define NBLK_MAX 3907    // ceil(500000/128)

#define AS_STRIDE 68     // [KC][68] floats for A chunk (64 q + pad, 16B-aligned rows)
#define BS_STRIDE 132    // [KC][132] floats for B chunk (128 n + pad, 16B-aligned rows)
#define D_STRIDE  129    // [64][129] score staging

// Scratch (no allocations allowed anywhere)
__device__ float g_qnT[HID * BQ];                    // normalized queries, transposed [k][q]
__device__ float g_pscore[BQ * NBLK_MAX * KTOP];     // per-block top-5 scores
__device__ int   g_pidx[BQ * NBLK_MAX * KTOP];       // per-block top-5 indices

// ---------------------------------------------------------------------------
// Kernel 1: L2-normalize queries, store transposed [k][q]
// ---------------------------------------------------------------------------
__global__ void qnorm_kernel(const float* __restrict__ qe) {
    __shared__ float red[8];
    int q = blockIdx.x, tid = threadIdx.x;
    float v0 = qe[q * HID + tid];
    float v1 = qe[q * HID + tid + 256];
    float v2 = qe[q * HID + tid + 512];
    float ss = v0 * v0 + v1 * v1 + v2 * v2;
    #pragma unroll
    for (int o = 16; o; o >>= 1) ss += __shfl_xor_sync(0xffffffffu, ss, o);
    if ((tid & 31) == 0) red[tid >> 5] = ss;
    __syncthreads();
    float tot = 0.f;
    #pragma unroll
    for (int i = 0; i < 8; i++) tot += red[i];
    float r = 1.f / fmaxf(sqrtf(tot), 1e-12f);
    g_qnT[(tid      ) * BQ + q] = v0 * r;
    g_qnT[(tid + 256) * BQ + q] = v1 * r;
    g_qnT[(tid + 512) * BQ + q] = v2 * r;
}

// ---------------------------------------------------------------------------
// Kernel 2: main GEMM (packed fp32x2 FMA) + fused evidence norm + block top-5
// ---------------------------------------------------------------------------
__global__ __launch_bounds__(256)
void sim_kernel(const float* __restrict__ ev, int N) {
    // SMEM union: [As | Bs] during GEMM (6400 floats), Ds (8256) after final
    // sync, rnorm at [8448..8576). Total 8576 floats = 34304 bytes static.
    __shared__ float smem[8576];
    float* As = smem;
    float* Bs = smem + KC * AS_STRIDE;        // +2176
    float* Ds = smem;                         // reused after final sync
    float* rnorm = smem + 8448;

    int tid = threadIdx.x;
    int tq = tid & 7;        // 0..7  -> query pairs: queries tq*8 .. tq*8+7
    int te = tid >> 3;       // 0..31 -> evidence te*4 .. te*4+3
    int n0 = blockIdx.x * TILE_N;

    unsigned long long acc[4][4];             // 4 query-pairs x 4 evidence
    #pragma unroll
    for (int a = 0; a < 4; a++)
        #pragma unroll
        for (int b = 0; b < 4; b++) acc[a][b] = 0ull;
    float nsq[4] = {0.f, 0.f, 0.f, 0.f};

    for (int c = 0; c < NCHUNK; ++c) {
        int k0 = c * KC;
        // --- load A chunk (coalesced copy from transposed qnT) ---
        #pragma unroll
        for (int i = 0; i < 2; i++) {
            int f = tid + i * 256;            // float4 index, 512 total
            int k = f >> 4, q4 = (f & 15) << 2;
            float4 v = *(const float4*)&g_qnT[(k0 + k) * BQ + q4];
            *(float4*)&As[k * AS_STRIDE + q4] = v;
        }
        // --- load B chunk, transpose into [k][n], fuse sum-of-squares ---
        #pragma unroll
        for (int i = 0; i < 4; i++) {
            int f = tid + i * 256;            // 1024 float4 total
            int n = f >> 3, kk4 = (f & 7) << 2;
            int gn = n0 + n;
            float4 v = make_float4(0.f, 0.f, 0.f, 0.f);
            if (gn < N) v = *(const float4*)&ev[(size_t)gn * HID + k0 + kk4];
            Bs[(kk4 + 0) * BS_STRIDE + n] = v.x;
            Bs[(kk4 + 1) * BS_STRIDE + n] = v.y;
            Bs[(kk4 + 2) * BS_STRIDE + n] = v.z;
            Bs[(kk4 + 3) * BS_STRIDE + n] = v.w;
            nsq[i] += v.x * v.x + v.y * v.y + v.z * v.z + v.w * v.w;
        }
        __syncthreads();
        // --- compute: 16 packed f32x2 FMAs per k per thread ---
        #pragma unroll 8
        for (int k = 0; k < KC; ++k) {
            const float* arow = &As[k * AS_STRIDE + (tq << 3)];
            ulonglong2 aA = *(const ulonglong2*)(arow);      // LDS.128 -> 2 q-pairs
            ulonglong2 aB = *(const ulonglong2*)(arow + 4);
            unsigned long long ap[4] = {aA.x, aA.y, aB.x, aB.y};
            float4 bv = *(const float4*)&Bs[k * BS_STRIDE + (te << 2)];
            unsigned long long bb[4];
            unsigned u;
            u = __float_as_uint(bv.x); asm("mov.b64 %0, {%1,%1};" : "=l"(bb[0]) : "r"(u));
            u = __float_as_uint(bv.y); asm("mov.b64 %0, {%1,%1};" : "=l"(bb[1]) : "r"(u));
            u = __float_as_uint(bv.z); asm("mov.b64 %0, {%1,%1};" : "=l"(bb[2]) : "r"(u));
            u = __float_as_uint(bv.w); asm("mov.b64 %0, {%1,%1};" : "=l"(bb[3]) : "r"(u));
            #pragma unroll
            for (int qi = 0; qi < 4; qi++)
                #pragma unroll
                for (int ei = 0; ei < 4; ei++)
                    asm("fma.rn.f32x2 %0, %1, %2, %0;"
                        : "+l"(acc[qi][ei]) : "l"(ap[qi]), "l"(bb[ei]));
        }
        __syncthreads();
    }

    // --- finalize evidence norms (groups of 8 lanes own one row each) ---
    #pragma unroll
    for (int i = 0; i < 4; i++) {
        float v = nsq[i];
        v += __shfl_down_sync(0xffffffffu, v, 4, 8);
        v += __shfl_down_sync(0xffffffffu, v, 2, 8);
        v += __shfl_down_sync(0xffffffffu, v, 1, 8);
        if ((tid & 7) == 0) {
            int n = (tid >> 3) + i * 32;
            rnorm[n] = 1.f / fmaxf(sqrtf(v), 1e-12f);
        }
    }
    __syncthreads();

    // --- stage scores into Ds (reusing As/Bs memory) ---
    #pragma unroll
    for (int qi = 0; qi < 4; qi++) {
        #pragma unroll
        for (int ei = 0; ei < 4; ei++) {
            int n = (te << 2) + ei;
            int q = (tq << 3) + (qi << 1);
            bool valid = (n0 + n) < N;
            float rn = rnorm[n];
            float lo = __uint_as_float((unsigned)(acc[qi][ei] & 0xffffffffull));
            float hi = __uint_as_float((unsigned)(acc[qi][ei] >> 32));
            Ds[q * D_STRIDE + n]       = valid ? lo * rn : -FLT_MAX;
            Ds[(q + 1) * D_STRIDE + n] = valid ? hi * rn : -FLT_MAX;
        }
    }
    __syncthreads();

    // --- per-block top-5 per query: warp w owns queries w*8..w*8+7 ---
    int w = tid >> 5, lane = tid & 31;
    for (int j = 0; j < 8; j++) {
        int q = w * 8 + j;
        float c0 = Ds[q * D_STRIDE + lane];
        float c1 = Ds[q * D_STRIDE + lane + 32];
        float c2 = Ds[q * D_STRIDE + lane + 64];
        float c3 = Ds[q * D_STRIDE + lane + 96];
        int i0 = lane, i1 = lane + 32, i2 = lane + 64, i3 = lane + 96;
        #pragma unroll
        for (int t = 0; t < 5; t++) {
            float bs = c0; int bi = i0;
            if (c1 > bs || (c1 == bs && i1 < bi)) { bs = c1; bi = i1; }
            if (c2 > bs || (c2 == bs && i2 < bi)) { bs = c2; bi = i2; }
            if (c3 > bs || (c3 == bs && i3 < bi)) { bs = c3; bi = i3; }
            #pragma unroll
            for (int o = 16; o; o >>= 1) {
                float os = __shfl_xor_sync(0xffffffffu, bs, o);
                int   oi = __shfl_xor_sync(0xffffffffu, bi, o);
                if (os > bs || (os == bs && oi < bi)) { bs = os; bi = oi; }
            }
            if (lane == 0) {
                size_t p = ((size_t)q * gridDim.x + blockIdx.x) * KTOP + t;
                g_pscore[p] = bs;
                g_pidx[p]   = n0 + bi;
            }
            if      (i0 == bi) c0 = -FLT_MAX;
            else if (i1 == bi) c1 = -FLT_MAX;
            else if (i2 == bi) c2 = -FLT_MAX;
            else if (i3 == bi) c3 = -FLT_MAX;
        }
    }
}

// ---------------------------------------------------------------------------
// Kernel 3: merge per-block partials -> global top-5 per query
// ---------------------------------------------------------------------------
__device__ __forceinline__ void ins5(float* s, int* id, float sc, int ix) {
    // keep descending; tie -> lower index first (matches jax.lax.top_k)
    if (!(sc > s[4] || (sc == s[4] && ix < id[4]))) return;
    int j = 4;
    while (j > 0 && (sc > s[j - 1] || (sc == s[j - 1] && ix < id[j - 1]))) {
        s[j] = s[j - 1]; id[j] = id[j - 1]; --j;
    }
    s[j] = sc; id[j] = ix;
}

__global__ void merge_kernel(float* __restrict__ out, int nblk, int out_size) {
    __shared__ float ss[256 * KTOP];
    __shared__ int   si[256 * KTOP];
    int q = blockIdx.x, tid = threadIdx.x;
    int M = nblk * KTOP;

    float s[KTOP]; int id[KTOP];
    #pragma unroll
    for (int j = 0; j < KTOP; j++) { s[j] = -FLT_MAX; id[j] = 0x7fffffff; }
    size_t base = (size_t)q * nblk * KTOP;
    for (int c = tid; c < M; c += 256)
        ins5(s, id, g_pscore[base + c], g_pidx[base + c]);
    #pragma unroll
    for (int j = 0; j < KTOP; j++) { ss[tid * KTOP + j] = s[j]; si[tid * KTOP + j] = id[j]; }
    __syncthreads();

    if (tid < 32) {
        float s2[KTOP]; int i2[KTOP];
        #pragma unroll
        for (int j = 0; j < KTOP; j++) { s2[j] = -FLT_MAX; i2[j] = 0x7fffffff; }
        for (int c = tid; c < 256 * KTOP; c += 32) ins5(s2, i2, ss[c], si[c]);
        int p = 0;
        #pragma unroll
        for (int t = 0; t < KTOP; t++) {
            float bs = (p < KTOP) ? s2[p] : -FLT_MAX;
            int   bi = (p < KTOP) ? i2[p] : 0x7fffffff;
            float cs = bs; int ci = bi;
            #pragma unroll
            for (int o = 16; o; o >>= 1) {
                float os = __shfl_xor_sync(0xffffffffu, cs, o);
                int   oi = __shfl_xor_sync(0xffffffffu, ci, o);
                if (os > cs || (os == cs && oi < ci)) { cs = os; ci = oi; }
            }
            if (bs == cs && bi == ci) ++p;   // winner lane pops (indices unique)
            if (tid == 0) {
                int pi = q * KTOP + t;             // indices region
                int ps = BQ * KTOP + q * KTOP + t; // scores region
                if (pi < out_size) out[pi] = (float)ci;
                if (ps < out_size) out[ps] = cs;
            }
        }
    }
}

// ---------------------------------------------------------------------------
extern "C" void kernel_launch(void* const* d_in, const int* in_sizes, int n_in,
                              void* d_out, int out_size) {
    (void)n_in;
    const float* qe = (const float*)d_in[0];   // [64, 768] f32
    const float* ev = (const float*)d_in[1];   // [500000, 768] f32
    float* out = (float*)d_out;                // [320 idx][320 scores] f32

    int N = in_sizes[1] / HID;
    int nblk = (N + TILE_N - 1) / TILE_N;
    if (nblk > NBLK_MAX) nblk = NBLK_MAX;

    qnorm_kernel<<<BQ, 256>>>(qe);
    sim_kernel<<<nblk, 256>>>(ev, N);
    merge_kernel<<<BQ, 256>>>(out, nblk, out_size);
}

// round 7
// speedup vs baseline: 1.2590x; 1.2590x over previous
#include <cuda_runtime.h>
#include <cuda_bf16.h>
#include <float.h>
#include <stdint.h>

// Problem constants
#define BQ     64        // queries
#define HID    768       // hidden
#define KTOP   5
#define TILE_N 128       // evidence rows per block
#define KC     16        // K-chunk
#define NCHUNK (HID / KC)        // 48
#define NBLK_MAX 3907            // ceil(500000/128)
#define THREADS 128

#define A_STRIDE 20      // [64][20] floats per A buffer (16 k + pad; 20 mod 32 spreads banks)
#define B_STRIDE 20      // [128][20] floats per B buffer
#define D_STRIDE 129     // [64][129] score staging

// SMEM float offsets
#define AS_OFF(buf) ((buf) * (BQ * A_STRIDE))                  // 0 / 1280
#define BS_OFF(buf) (2 * BQ * A_STRIDE + (buf) * (TILE_N * B_STRIDE)) // 2560 / 5120
#define RN_OFF      8256                                        // rnorm after Ds
#define SMEM_FLOATS 8448

// Scratch (no allocations allowed anywhere)
__device__ float g_qn[BQ * HID];                     // normalized queries, row-major
__device__ float g_pscore[BQ * NBLK_MAX * KTOP];     // per-block top-5 scores
__device__ int   g_pidx[BQ * NBLK_MAX * KTOP];       // per-block top-5 indices

__device__ __forceinline__ float lo32(unsigned long long v) {
    return __uint_as_float((unsigned)(v & 0xffffffffull));
}
__device__ __forceinline__ float hi32(unsigned long long v) {
    return __uint_as_float((unsigned)(v >> 32));
}

// ---------------------------------------------------------------------------
// Kernel 1: L2-normalize queries, row-major output
// ---------------------------------------------------------------------------
__global__ void qnorm_kernel(const float* __restrict__ qe) {
    __shared__ float red[8];
    int q = blockIdx.x, tid = threadIdx.x;
    float v0 = qe[q * HID + tid];
    float v1 = qe[q * HID + tid + 256];
    float v2 = qe[q * HID + tid + 512];
    float ss = v0 * v0 + v1 * v1 + v2 * v2;
    #pragma unroll
    for (int o = 16; o; o >>= 1) ss += __shfl_xor_sync(0xffffffffu, ss, o);
    if ((tid & 31) == 0) red[tid >> 5] = ss;
    __syncthreads();
    float tot = 0.f;
    #pragma unroll
    for (int i = 0; i < 8; i++) tot += red[i];
    float r = 1.f / fmaxf(sqrtf(tot), 1e-12f);
    g_qn[q * HID + tid      ] = v0 * r;
    g_qn[q * HID + tid + 256] = v1 * r;
    g_qn[q * HID + tid + 512] = v2 * r;
}

// ---------------------------------------------------------------------------
// Kernel 2: main GEMM — k-paired FFMA2, double-buffered, fused norms + top-5
//   128 threads: tq = tid&7 (8 q-groups), te = tid>>3 (0..15, 8 evidence each)
//   per thread: 8 queries (q = qi*8+tq) x 8 evidence (n = te*8+ei)
// ---------------------------------------------------------------------------
__global__ __launch_bounds__(THREADS)
void sim_kernel(const float* __restrict__ ev, int N) {
    __shared__ float smem[SMEM_FLOATS];
    float* Ds = smem;
    float* rnorm = smem + RN_OFF;

    int tid = threadIdx.x;
    int tq = tid & 7;
    int te = tid >> 3;
    int n0 = blockIdx.x * TILE_N;

    unsigned long long acc[8][8];       // f32x2 over (k even, k odd)
    #pragma unroll
    for (int a = 0; a < 8; a++)
        #pragma unroll
        for (int b = 0; b < 8; b++) acc[a][b] = 0ull;
    float nsq[4] = {0.f, 0.f, 0.f, 0.f};

    float4 breg[4], areg[2];

    // ---- prologue: load + store chunk 0 ----
    {
        int k0 = 0;
        #pragma unroll
        for (int i = 0; i < 4; i++) {
            int f = tid + (i << 7);
            int n = f >> 2, col = (f & 3) << 2;
            int gn = n0 + n;
            breg[i] = make_float4(0.f, 0.f, 0.f, 0.f);
            if (gn < N) breg[i] = *(const float4*)&ev[(size_t)gn * HID + k0 + col];
        }
        #pragma unroll
        for (int i = 0; i < 2; i++) {
            int f = tid + (i << 7);
            int q = f >> 2, col = (f & 3) << 2;
            areg[i] = *(const float4*)&g_qn[q * HID + k0 + col];
        }
        #pragma unroll
        for (int i = 0; i < 4; i++) {
            int f = tid + (i << 7);
            int n = f >> 2, col = (f & 3) << 2;
            *(float4*)&smem[BS_OFF(0) + n * B_STRIDE + col] = breg[i];
            nsq[i] += breg[i].x * breg[i].x + breg[i].y * breg[i].y
                    + breg[i].z * breg[i].z + breg[i].w * breg[i].w;
        }
        #pragma unroll
        for (int i = 0; i < 2; i++) {
            int f = tid + (i << 7);
            int q = f >> 2, col = (f & 3) << 2;
            *(float4*)&smem[AS_OFF(0) + q * A_STRIDE + col] = areg[i];
        }
    }
    __syncthreads();

    // ---- main loop: compute(c) on buf cur, prefetch+store (c+1) into nxt ----
    for (int c = 0; c < NCHUNK; ++c) {
        int cur = c & 1, nxt = cur ^ 1;
        bool have_next = (c + 1 < NCHUNK);
        if (have_next) {
            int k0 = (c + 1) * KC;
            #pragma unroll
            for (int i = 0; i < 4; i++) {
                int f = tid + (i << 7);
                int n = f >> 2, col = (f & 3) << 2;
                int gn = n0 + n;
                breg[i] = make_float4(0.f, 0.f, 0.f, 0.f);
                if (gn < N) breg[i] = *(const float4*)&ev[(size_t)gn * HID + k0 + col];
            }
            #pragma unroll
            for (int i = 0; i < 2; i++) {
                int f = tid + (i << 7);
                int q = f >> 2, col = (f & 3) << 2;
                areg[i] = *(const float4*)&g_qn[q * HID + k0 + col];
            }
        }

        // compute over current buffer: 4 groups of 4 k each
        const float* Ab = smem + AS_OFF(cur);
        const float* Bb = smem + BS_OFF(cur);
        #pragma unroll
        for (int k4 = 0; k4 < 4; k4++) {
            ulonglong2 a2[8];
            #pragma unroll
            for (int qi = 0; qi < 8; qi++)
                a2[qi] = *(const ulonglong2*)&Ab[((qi << 3) + tq) * A_STRIDE + (k4 << 2)];
            #pragma unroll
            for (int ei = 0; ei < 8; ei++) {
                ulonglong2 b2 = *(const ulonglong2*)&Bb[((te << 3) + ei) * B_STRIDE + (k4 << 2)];
                #pragma unroll
                for (int qi = 0; qi < 8; qi++) {
                    asm("fma.rn.f32x2 %0, %1, %2, %0;"
                        : "+l"(acc[qi][ei]) : "l"(a2[qi].x), "l"(b2.x));
                    asm("fma.rn.f32x2 %0, %1, %2, %0;"
                        : "+l"(acc[qi][ei]) : "l"(a2[qi].y), "l"(b2.y));
                }
            }
        }

        if (have_next) {   // store into the buffer compute(c) did NOT read
            #pragma unroll
            for (int i = 0; i < 4; i++) {
                int f = tid + (i << 7);
                int n = f >> 2, col = (f & 3) << 2;
                *(float4*)&smem[BS_OFF(nxt) + n * B_STRIDE + col] = breg[i];
                nsq[i] += breg[i].x * breg[i].x + breg[i].y * breg[i].y
                        + breg[i].z * breg[i].z + breg[i].w * breg[i].w;
            }
            #pragma unroll
            for (int i = 0; i < 2; i++) {
                int f = tid + (i << 7);
                int q = f >> 2, col = (f & 3) << 2;
                *(float4*)&smem[AS_OFF(nxt) + q * A_STRIDE + col] = areg[i];
            }
        }
        __syncthreads();
    }

    // ---- evidence norms: reduce nsq over the 4 threads sharing each row ----
    #pragma unroll
    for (int i = 0; i < 4; i++) {
        float v = nsq[i];
        v += __shfl_xor_sync(0xffffffffu, v, 1, 4);
        v += __shfl_xor_sync(0xffffffffu, v, 2, 4);
        if ((tid & 3) == 0)
            rnorm[(tid >> 2) + (i << 5)] = 1.f / fmaxf(sqrtf(v), 1e-12f);
    }
    __syncthreads();

    // ---- stage scores into Ds (overwrites A/B buffers; compute all done) ----
    #pragma unroll
    for (int qi = 0; qi < 8; qi++) {
        int q = (qi << 3) + tq;
        #pragma unroll
        for (int ei = 0; ei < 8; ei++) {
            int n = (te << 3) + ei;
            float s = (lo32(acc[qi][ei]) + hi32(acc[qi][ei])) * rnorm[n];
            Ds[q * D_STRIDE + n] = (n0 + n < N) ? s : -FLT_MAX;
        }
    }
    __syncthreads();

    // ---- per-block top-5 per query: warp w owns queries w*16 .. w*16+15 ----
    int w = tid >> 5, lane = tid & 31;
    for (int j = 0; j < 16; j++) {
        int q = w * 16 + j;
        float c0 = Ds[q * D_STRIDE + lane];
        float c1 = Ds[q * D_STRIDE + lane + 32];
        float c2 = Ds[q * D_STRIDE + lane + 64];
        float c3 = Ds[q * D_STRIDE + lane + 96];
        int i0 = lane, i1 = lane + 32, i2 = lane + 64, i3 = lane + 96;
        #pragma unroll
        for (int t = 0; t < KTOP; t++) {
            float bs = c0; int bi = i0;
            if (c1 > bs || (c1 == bs && i1 < bi)) { bs = c1; bi = i1; }
            if (c2 > bs || (c2 == bs && i2 < bi)) { bs = c2; bi = i2; }
            if (c3 > bs || (c3 == bs && i3 < bi)) { bs = c3; bi = i3; }
            #pragma unroll
            for (int o = 16; o; o >>= 1) {
                float os = __shfl_xor_sync(0xffffffffu, bs, o);
                int   oi = __shfl_xor_sync(0xffffffffu, bi, o);
                if (os > bs || (os == bs && oi < bi)) { bs = os; bi = oi; }
            }
            if (lane == 0) {
                size_t p = ((size_t)q * gridDim.x + blockIdx.x) * KTOP + t;
                g_pscore[p] = bs;
                g_pidx[p]   = n0 + bi;
            }
            if      (i0 == bi) c0 = -FLT_MAX;
            else if (i1 == bi) c1 = -FLT_MAX;
            else if (i2 == bi) c2 = -FLT_MAX;
            else if (i3 == bi) c3 = -FLT_MAX;
        }
    }
}

// ---------------------------------------------------------------------------
// Kernel 3: merge per-block partials -> global top-5 per query
// ---------------------------------------------------------------------------
__device__ __forceinline__ void ins5(float* s, int* id, float sc, int ix) {
    if (!(sc > s[4] || (sc == s[4] && ix < id[4]))) return;
    int j = 4;
    while (j > 0 && (sc > s[j - 1] || (sc == s[j - 1] && ix < id[j - 1]))) {
        s[j] = s[j - 1]; id[j] = id[j - 1]; --j;
    }
    s[j] = sc; id[j] = ix;
}

__global__ void merge_kernel(float* __restrict__ out, int nblk, int out_size) {
    __shared__ float ss[256 * KTOP];
    __shared__ int   si[256 * KTOP];
    int q = blockIdx.x, tid = threadIdx.x;
    int M = nblk * KTOP;

    float s[KTOP]; int id[KTOP];
    #pragma unroll
    for (int j = 0; j < KTOP; j++) { s[j] = -FLT_MAX; id[j] = 0x7fffffff; }
    size_t base = (size_t)q * nblk * KTOP;
    for (int c = tid; c < M; c += 256)
        ins5(s, id, g_pscore[base + c], g_pidx[base + c]);
    #pragma unroll
    for (int j = 0; j < KTOP; j++) { ss[tid * KTOP + j] = s[j]; si[tid * KTOP + j] = id[j]; }
    __syncthreads();

    if (tid < 32) {
        float s2[KTOP]; int i2[KTOP];
        #pragma unroll
        for (int j = 0; j < KTOP; j++) { s2[j] = -FLT_MAX; i2[j] = 0x7fffffff; }
        for (int c = tid; c < 256 * KTOP; c += 32) ins5(s2, i2, ss[c], si[c]);
        int p = 0;
        #pragma unroll
        for (int t = 0; t < KTOP; t++) {
            float bs = (p < KTOP) ? s2[p] : -FLT_MAX;
            int   bi = (p < KTOP) ? i2[p] : 0x7fffffff;
            float cs = bs; int ci = bi;
            #pragma unroll
            for (int o = 16; o; o >>= 1) {
                float os = __shfl_xor_sync(0xffffffffu, cs, o);
                int   oi = __shfl_xor_sync(0xffffffffu, ci, o);
                if (os > cs || (os == cs && oi < ci)) { cs = os; ci = oi; }
            }
            if (bs == cs && bi == ci) ++p;   // winner lane pops (indices unique)
            if (tid == 0) {
                int pi = q * KTOP + t;             // indices region
                int ps = BQ * KTOP + q * KTOP + t; // scores region
                if (pi < out_size) out[pi] = (float)ci;
                if (ps < out_size) out[ps] = cs;
            }
        }
    }
}

// ---------------------------------------------------------------------------
extern "C" void kernel_launch(void* const* d_in, const int* in_sizes, int n_in,
                              void* d_out, int out_size) {
    (void)n_in;
    const float* qe = (const float*)d_in[0];   // [64, 768] f32
    const float* ev = (const float*)d_in[1];   // [500000, 768] f32
    float* out = (float*)d_out;                // [320 idx][320 scores] f32

    int N = in_sizes[1] / HID;
    int nblk = (N + TILE_N - 1) / TILE_N;
    if (nblk > NBLK_MAX) nblk = NBLK_MAX;

    qnorm_kernel<<<BQ, 256>>>(qe);
    sim_kernel<<<nblk, THREADS>>>(ev, N);
    merge_kernel<<<BQ, 256>>>(out, nblk, out_size);
}

// round 9
// speedup vs baseline: 1.7547x; 1.3937x over previous
#include <cuda_runtime.h>
#include <cuda_bf16.h>
#include <float.h>
#include <stdint.h>

// ---------------- problem constants ----------------
#define BQ     64
#define HID    768
#define KTOP   5
#define TILE_N 128              // evidence rows per CTA
#define CHK    48               // K per SMEM chunk (3 k16 steps)
#define NCH    (HID / CHK)      // 16
#define NBLK_MAX 3907
#define NCAND  16               // exact-rescore candidates per query
#define DSTR   132              // Ds[q][m] stride (floats)

#define A_STRIDE_B 112          // bytes per row in smem (96B data + 16 pad)
#define A_BUF_B (TILE_N * A_STRIDE_B)   // 14336
#define B_BUF_B (BQ * A_STRIDE_B)       // 7168
#define BS_BASE (2 * A_BUF_B)           // 28672
#define SMEM_BYTES (2 * A_BUF_B + 2 * B_BUF_B)  // 43008 (Ds 33792 fits in union)

// ---------------- device scratch ----------------
__device__ float g_qn[BQ * HID];                          // normalized queries fp32
__device__ __align__(16) unsigned short g_qbf[BQ * HID];  // normalized queries bf16
__device__ float g_pscore[BQ * NBLK_MAX * KTOP];
__device__ int   g_pidx[BQ * NBLK_MAX * KTOP];
__device__ int   g_cand[BQ * NCAND];

// ---------------- helpers ----------------
__device__ __forceinline__ uint32_t smem_u32(const void* p) {
    uint32_t a;
    asm("{ .reg .u64 t; cvta.to.shared.u64 t, %1; cvt.u32.u64 %0, t; }" : "=r"(a) : "l"(p));
    return a;
}
__device__ __forceinline__ void ldsm_x4(uint32_t a, uint32_t r[4]) {
    asm volatile("ldmatrix.sync.aligned.m8n8.x4.shared.b16 {%0,%1,%2,%3}, [%4];"
                 : "=r"(r[0]), "=r"(r[1]), "=r"(r[2]), "=r"(r[3]) : "r"(a));
}
__device__ __forceinline__ void ldsm_x2(uint32_t a, uint32_t r[2]) {
    asm volatile("ldmatrix.sync.aligned.m8n8.x2.shared.b16 {%0,%1}, [%2];"
                 : "=r"(r[0]), "=r"(r[1]) : "r"(a));
}
__device__ __forceinline__ void mma_bf16(float c[4], const uint32_t a[4], const uint32_t b[2]) {
    asm volatile("mma.sync.aligned.m16n8k16.row.col.f32.bf16.bf16.f32 "
        "{%0,%1,%2,%3}, {%4,%5,%6,%7}, {%8,%9}, {%0,%1,%2,%3};"
        : "+f"(c[0]), "+f"(c[1]), "+f"(c[2]), "+f"(c[3])
        : "r"(a[0]), "r"(a[1]), "r"(a[2]), "r"(a[3]), "r"(b[0]), "r"(b[1]));
}
__device__ __forceinline__ uint2 cvt4_bf16(float4 v) {
    uint2 r;
    asm("cvt.rn.bf16x2.f32 %0, %1, %2;" : "=r"(r.x) : "f"(v.y), "f"(v.x));
    asm("cvt.rn.bf16x2.f32 %0, %1, %2;" : "=r"(r.y) : "f"(v.w), "f"(v.z));
    return r;
}

// ---------------------------------------------------------------------------
// K1: normalize queries -> fp32 (rescore) + bf16 row-major (GEMM B)
// ---------------------------------------------------------------------------
__global__ void qnorm_kernel(const float* __restrict__ qe) {
    __shared__ float red[8];
    int q = blockIdx.x, tid = threadIdx.x;
    float v0 = qe[q * HID + tid];
    float v1 = qe[q * HID + tid + 256];
    float v2 = qe[q * HID + tid + 512];
    float ss = v0 * v0 + v1 * v1 + v2 * v2;
    #pragma unroll
    for (int o = 16; o; o >>= 1) ss += __shfl_xor_sync(0xffffffffu, ss, o);
    if ((tid & 31) == 0) red[tid >> 5] = ss;
    __syncthreads();
    float tot = 0.f;
    #pragma unroll
    for (int i = 0; i < 8; i++) tot += red[i];
    float r = 1.f / fmaxf(sqrtf(tot), 1e-12f);
    #pragma unroll
    for (int part = 0; part < 3; part++) {
        int k = tid + part * 256;
        float val = (part == 0 ? v0 : (part == 1 ? v1 : v2)) * r;
        g_qn[q * HID + k] = val;
        __nv_bfloat16 b = __float2bfloat16(val);
        g_qbf[q * HID + k] = *(unsigned short*)&b;
    }
}

// ---------------------------------------------------------------------------
// K2: bf16 mma.sync GEMM + fused fp32 norms + per-block approx top-5
//   256 threads (8 warps). Warp w: evidence rows 16w..16w+15 (m16 tile),
//   8 n-tiles of 8 queries. Double-buffered K chunks of 48.
// ---------------------------------------------------------------------------
__global__ __launch_bounds__(256)
void sim_kernel(const float* __restrict__ ev, int N) {
    __shared__ __align__(16) unsigned char sm[SMEM_BYTES];
    __shared__ float s_rnorm[TILE_N];

    int tid = threadIdx.x, w = tid >> 5, lane = tid & 31;
    int n0 = blockIdx.x * TILE_N;
    uint32_t smb = smem_u32(sm);

    // A loading: thread pair (2r, 2r+1) owns evidence row r
    int arow = tid >> 1, ahalf = tid & 1;
    bool aok = (n0 + arow) < N;
    const float* evrow = ev + (size_t)(n0 + arow) * HID;

    float4 av[6];
    uint2  bv[3];
    float  nsq = 0.f;
    float  acc[8][4];
    #pragma unroll
    for (int t = 0; t < 8; t++)
        #pragma unroll
        for (int j = 0; j < 4; j++) acc[t][j] = 0.f;

    // ldmatrix base addresses
    uint32_t aAddrBase = smb + (uint32_t)(16 * w + (lane & 15)) * A_STRIDE_B
                             + (uint32_t)(lane >> 4) * 16;
    uint32_t bAddrBase = smb + BS_BASE + (uint32_t)(lane & 7) * A_STRIDE_B
                             + (uint32_t)((lane >> 3) & 1) * 16;

    // --- prologue: chunk 0 ---
    {
        #pragma unroll
        for (int j = 0; j < 6; j++) {
            av[j] = make_float4(0.f, 0.f, 0.f, 0.f);
            if (aok) av[j] = *(const float4*)&evrow[8 * j + 4 * ahalf];
        }
        #pragma unroll
        for (int i = 0; i < 3; i++) {
            int task = tid + (i << 8);
            int q = task / 12, g = task - q * 12;
            bv[i] = *(const uint2*)&g_qbf[q * HID + 4 * g];
        }
        unsigned char* Ab = sm;
        #pragma unroll
        for (int j = 0; j < 6; j++) {
            float4 v = av[j];
            nsq += v.x * v.x + v.y * v.y + v.z * v.z + v.w * v.w;
            *(uint2*)(Ab + arow * A_STRIDE_B + (2 * j + ahalf) * 8) = cvt4_bf16(v);
        }
        unsigned char* Bb = sm + BS_BASE;
        #pragma unroll
        for (int i = 0; i < 3; i++) {
            int task = tid + (i << 8);
            int q = task / 12, g = task - q * 12;
            *(uint2*)(Bb + q * A_STRIDE_B + g * 8) = bv[i];
        }
    }
    __syncthreads();

    // --- main loop ---
    for (int c = 0; c < NCH; ++c) {
        int buf = c & 1;
        if (c + 1 < NCH) {
            int k0 = (c + 1) * CHK;
            #pragma unroll
            for (int j = 0; j < 6; j++) {
                av[j] = make_float4(0.f, 0.f, 0.f, 0.f);
                if (aok) av[j] = *(const float4*)&evrow[k0 + 8 * j + 4 * ahalf];
            }
            #pragma unroll
            for (int i = 0; i < 3; i++) {
                int task = tid + (i << 8);
                int q = task / 12, g = task - q * 12;
                bv[i] = *(const uint2*)&g_qbf[q * HID + k0 + 4 * g];
            }
        }

        // compute current buffer: 3 k16 steps x 8 n-tiles
        {
            uint32_t ab = aAddrBase + (uint32_t)buf * A_BUF_B;
            uint32_t bb = bAddrBase + (uint32_t)buf * B_BUF_B;
            #pragma unroll
            for (int s = 0; s < 3; s++) {
                uint32_t af[4];
                ldsm_x4(ab + s * 32, af);
                #pragma unroll
                for (int t = 0; t < 8; t++) {
                    uint32_t bf[2];
                    ldsm_x2(bb + (uint32_t)t * 8 * A_STRIDE_B + s * 32, bf);
                    mma_bf16(acc[t], af, bf);
                }
            }
        }

        if (c + 1 < NCH) {   // store prefetched chunk into the other buffer
            int nxt = buf ^ 1;
            unsigned char* Ab = sm + nxt * A_BUF_B;
            #pragma unroll
            for (int j = 0; j < 6; j++) {
                float4 v = av[j];
                nsq += v.x * v.x + v.y * v.y + v.z * v.z + v.w * v.w;
                *(uint2*)(Ab + arow * A_STRIDE_B + (2 * j + ahalf) * 8) = cvt4_bf16(v);
            }
            unsigned char* Bb = sm + BS_BASE + nxt * B_BUF_B;
            #pragma unroll
            for (int i = 0; i < 3; i++) {
                int task = tid + (i << 8);
                int q = task / 12, g = task - q * 12;
                *(uint2*)(Bb + q * A_STRIDE_B + g * 8) = bv[i];
            }
        }
        __syncthreads();
    }

    // --- evidence norms: pair-reduce (threads 2r, 2r+1 share row r) ---
    float vtot = nsq + __shfl_xor_sync(0xffffffffu, nsq, 1);
    if (ahalf == 0) s_rnorm[arow] = 1.f / fmaxf(sqrtf(vtot), 1e-12f);
    __syncthreads();

    // --- stage scores Ds[q][m] (reuse smem union) ---
    float* Ds = (float*)sm;
    int mlo = 16 * w + (lane >> 2), mhi = mlo + 8;
    float rlo = s_rnorm[mlo], rhi = s_rnorm[mhi];
    bool vlo = (n0 + mlo) < N, vhi = (n0 + mhi) < N;
    #pragma unroll
    for (int t = 0; t < 8; t++) {
        int n = 8 * t + 2 * (lane & 3);
        Ds[n * DSTR + mlo]       = vlo ? acc[t][0] * rlo : -FLT_MAX;
        Ds[(n + 1) * DSTR + mlo] = vlo ? acc[t][1] * rlo : -FLT_MAX;
        Ds[n * DSTR + mhi]       = vhi ? acc[t][2] * rhi : -FLT_MAX;
        Ds[(n + 1) * DSTR + mhi] = vhi ? acc[t][3] * rhi : -FLT_MAX;
    }
    __syncthreads();

    // --- per-block approx top-5: warp w owns queries 8w..8w+7 ---
    for (int j = 0; j < 8; j++) {
        int q = w * 8 + j;
        float c0 = Ds[q * DSTR + lane];
        float c1 = Ds[q * DSTR + lane + 32];
        float c2 = Ds[q * DSTR + lane + 64];
        float c3 = Ds[q * DSTR + lane + 96];
        int i0 = lane, i1 = lane + 32, i2 = lane + 64, i3 = lane + 96;
        #pragma unroll
        for (int t = 0; t < KTOP; t++) {
            float bs = c0; int bi = i0;
            if (c1 > bs || (c1 == bs && i1 < bi)) { bs = c1; bi = i1; }
            if (c2 > bs || (c2 == bs && i2 < bi)) { bs = c2; bi = i2; }
            if (c3 > bs || (c3 == bs && i3 < bi)) { bs = c3; bi = i3; }
            #pragma unroll
            for (int o = 16; o; o >>= 1) {
                float os = __shfl_xor_sync(0xffffffffu, bs, o);
                int   oi = __shfl_xor_sync(0xffffffffu, bi, o);
                if (os > bs || (os == bs && oi < bi)) { bs = os; bi = oi; }
            }
            if (lane == 0) {
                size_t p = ((size_t)q * gridDim.x + blockIdx.x) * KTOP + t;
                g_pscore[p] = bs;
                g_pidx[p]   = n0 + bi;
            }
            if      (i0 == bi) c0 = -FLT_MAX;
            else if (i1 == bi) c1 = -FLT_MAX;
            else if (i2 == bi) c2 = -FLT_MAX;
            else if (i3 == bi) c3 = -FLT_MAX;
        }
    }
}

// ---------------------------------------------------------------------------
// K3: merge per-block partials -> global top-16 candidates per query
// ---------------------------------------------------------------------------
__device__ __forceinline__ void ins16(float* s, int* id, float sc, int ix) {
    if (!(sc > s[NCAND-1] || (sc == s[NCAND-1] && ix < id[NCAND-1]))) return;
    int j = NCAND - 1;
    while (j > 0 && (sc > s[j-1] || (sc == s[j-1] && ix < id[j-1]))) {
        s[j] = s[j-1]; id[j] = id[j-1]; --j;
    }
    s[j] = sc; id[j] = ix;
}

__global__ void merge_kernel(int nblk) {
    __shared__ float ss[256 * NCAND];
    __shared__ int   si[256 * NCAND];
    int q = blockIdx.x, tid = threadIdx.x;
    int M = nblk * KTOP;

    float s[NCAND]; int id[NCAND];
    #pragma unroll
    for (int j = 0; j < NCAND; j++) { s[j] = -FLT_MAX; id[j] = 0x7fffffff; }
    size_t bse = (size_t)q * nblk * KTOP;
    for (int c = tid; c < M; c += 256)
        ins16(s, id, g_pscore[bse + c], g_pidx[bse + c]);
    #pragma unroll
    for (int j = 0; j < NCAND; j++) { ss[tid*NCAND+j] = s[j]; si[tid*NCAND+j] = id[j]; }
    __syncthreads();

    if (tid < 32) {
        float s2[NCAND]; int i2[NCAND];
        #pragma unroll
        for (int j = 0; j < NCAND; j++) { s2[j] = -FLT_MAX; i2[j] = 0x7fffffff; }
        for (int c = tid; c < 256 * NCAND; c += 32) ins16(s2, i2, ss[c], si[c]);
        __syncwarp();
        #pragma unroll
        for (int j = 0; j < NCAND; j++) { ss[tid*NCAND+j] = s2[j]; si[tid*NCAND+j] = i2[j]; }
        __syncwarp();
        if (tid == 0) {
            float s3[NCAND]; int i3[NCAND];
            #pragma unroll
            for (int j = 0; j < NCAND; j++) { s3[j] = -FLT_MAX; i3[j] = 0x7fffffff; }
            for (int c = 0; c < 32 * NCAND; c++) ins16(s3, i3, ss[c], si[c]);
            #pragma unroll
            for (int j = 0; j < NCAND; j++) g_cand[q * NCAND + j] = i3[j];
        }
    }
}

// ---------------------------------------------------------------------------
// K4: exact fp32 rescore of 16 candidates per query -> final top-5
// ---------------------------------------------------------------------------
__global__ void rescore_kernel(const float* __restrict__ ev,
                               float* __restrict__ out, int out_size) {
    __shared__ float cs[NCAND];
    int q = blockIdx.x, tid = threadIdx.x;
    int w = tid >> 5, lane = tid & 31;

    for (int t = 0; t < 4; t++) {
        int c = w * 4 + t;
        int idx = g_cand[q * NCAND + c];
        const float* e = &ev[(size_t)idx * HID];
        const float* qv = &g_qn[q * HID];
        float dot = 0.f, ssq = 0.f;
        #pragma unroll
        for (int kk = 0; kk < HID / 32; kk++) {
            float x = e[lane + kk * 32];
            dot += x * qv[lane + kk * 32];
            ssq += x * x;
        }
        #pragma unroll
        for (int o = 16; o; o >>= 1) {
            dot += __shfl_xor_sync(0xffffffffu, dot, o);
            ssq += __shfl_xor_sync(0xffffffffu, ssq, o);
        }
        if (lane == 0) cs[c] = dot / fmaxf(sqrtf(ssq), 1e-12f);
    }
    __syncthreads();

    if (w == 0) {
        float sc = (lane < NCAND) ? cs[lane] : -FLT_MAX;
        int   ix = (lane < NCAND) ? g_cand[q * NCAND + lane] : 0x7fffffff;
        #pragma unroll
        for (int t = 0; t < KTOP; t++) {
            float bs = sc; int bi = ix;
            #pragma unroll
            for (int o = 16; o; o >>= 1) {
                float os = __shfl_xor_sync(0xffffffffu, bs, o);
                int   oi = __shfl_xor_sync(0xffffffffu, bi, o);
                if (os > bs || (os == bs && oi < bi)) { bs = os; bi = oi; }
            }
            if (lane == 0) {
                int pi = q * KTOP + t;
                int ps = BQ * KTOP + q * KTOP + t;
                if (pi < out_size) out[pi] = (float)bi;
                if (ps < out_size) out[ps] = bs;
            }
            if (ix == bi) sc = -FLT_MAX;   // winner pops (indices unique)
        }
    }
}

// ---------------------------------------------------------------------------
extern "C" void kernel_launch(void* const* d_in, const int* in_sizes, int n_in,
                              void* d_out, int out_size) {
    (void)n_in;
    const float* qe = (const float*)d_in[0];
    const float* ev = (const float*)d_in[1];
    float* out = (float*)d_out;

    int N = in_sizes[1] / HID;
    int nblk = (N + TILE_N - 1) / TILE_N;
    if (nblk > NBLK_MAX) nblk = NBLK_MAX;

    qnorm_kernel<<<BQ, 256>>>(qe);
    sim_kernel<<<nblk, 256>>>(ev, N);
    merge_kernel<<<BQ, 256>>>(nblk);
    rescore_kernel<<<BQ, 128>>>(ev, out, out_size);
}

// round 10
// speedup vs baseline: 2.0914x; 1.1919x over previous
#include <cuda_runtime.h>
#include <cuda_bf16.h>
#include <float.h>
#include <stdint.h>

// ---------------- problem constants ----------------
#define BQ     64
#define HID    768
#define KTOP   5
#define TILE_N 128              // evidence rows per CTA
#define CHK    64               // K per SMEM chunk (4 k16 steps)
#define NCH    (HID / CHK)      // 12
#define NBLK_MAX 3907
#define NCAND  16
#define DSTR   132              // Ds[q][m] stride (floats)

#define A_STR  144              // bytes per bf16 row (128 data + 16 pad)
#define A_BUF  (TILE_N * A_STR)     // 18432
#define B_BUF  (BQ * A_STR)         // 9216
#define B_BASE (2 * A_BUF)          // 36864
#define DYN_SMEM (2 * A_BUF + 2 * B_BUF)  // 55296 (Ds union: 33792 fits)

// ---------------- device scratch ----------------
__device__ float g_qn[BQ * HID];
__device__ __align__(16) unsigned short g_qbf[BQ * HID];
__device__ float g_pscore[BQ * NBLK_MAX * KTOP];
__device__ int   g_pidx[BQ * NBLK_MAX * KTOP];
__device__ int   g_cand[BQ * NCAND];

// ---------------- helpers ----------------
__device__ __forceinline__ uint32_t smem_u32(const void* p) {
    uint32_t a;
    asm("{ .reg .u64 t; cvta.to.shared.u64 t, %1; cvt.u32.u64 %0, t; }" : "=r"(a) : "l"(p));
    return a;
}
__device__ __forceinline__ void ldsm_x4(uint32_t a, uint32_t r[4]) {
    asm volatile("ldmatrix.sync.aligned.m8n8.x4.shared.b16 {%0,%1,%2,%3}, [%4];"
                 : "=r"(r[0]), "=r"(r[1]), "=r"(r[2]), "=r"(r[3]) : "r"(a));
}
__device__ __forceinline__ void mma_bf16(float c[4], const uint32_t a[4], const uint32_t b[2]) {
    asm volatile("mma.sync.aligned.m16n8k16.row.col.f32.bf16.bf16.f32 "
        "{%0,%1,%2,%3}, {%4,%5,%6,%7}, {%8,%9}, {%0,%1,%2,%3};"
        : "+f"(c[0]), "+f"(c[1]), "+f"(c[2]), "+f"(c[3])
        : "r"(a[0]), "r"(a[1]), "r"(a[2]), "r"(a[3]), "r"(b[0]), "r"(b[1]));
}
__device__ __forceinline__ uint2 cvt4_bf16(float4 v) {
    uint2 r;
    asm("cvt.rn.bf16x2.f32 %0, %1, %2;" : "=r"(r.x) : "f"(v.y), "f"(v.x));
    asm("cvt.rn.bf16x2.f32 %0, %1, %2;" : "=r"(r.y) : "f"(v.w), "f"(v.z));
    return r;
}
__device__ __forceinline__ void cpa16(uint32_t dst, const void* src) {
    asm volatile("cp.async.cg.shared.global [%0], [%1], 16;" :: "r"(dst), "l"(src) : "memory");
}
#define CP_COMMIT() asm volatile("cp.async.commit_group;" ::: "memory")
#define CP_WAIT0()  asm volatile("cp.async.wait_group 0;" ::: "memory")

// ---------------------------------------------------------------------------
// K1: normalize queries -> fp32 (rescore) + bf16 row-major (GEMM B)
// ---------------------------------------------------------------------------
__global__ void qnorm_kernel(const float* __restrict__ qe) {
    __shared__ float red[8];
    int q = blockIdx.x, tid = threadIdx.x;
    float v0 = qe[q * HID + tid];
    float v1 = qe[q * HID + tid + 256];
    float v2 = qe[q * HID + tid + 512];
    float ss = v0 * v0 + v1 * v1 + v2 * v2;
    #pragma unroll
    for (int o = 16; o; o >>= 1) ss += __shfl_xor_sync(0xffffffffu, ss, o);
    if ((tid & 31) == 0) red[tid >> 5] = ss;
    __syncthreads();
    float tot = 0.f;
    #pragma unroll
    for (int i = 0; i < 8; i++) tot += red[i];
    float r = 1.f / fmaxf(sqrtf(tot), 1e-12f);
    #pragma unroll
    for (int part = 0; part < 3; part++) {
        int k = tid + part * 256;
        float val = (part == 0 ? v0 : (part == 1 ? v1 : v2)) * r;
        g_qn[q * HID + k] = val;
        __nv_bfloat16 b = __float2bfloat16(val);
        g_qbf[q * HID + k] = *(unsigned short*)&b;
    }
}

// ---------------------------------------------------------------------------
// K2: bf16 mma.sync GEMM, coalesced A LDG, cp.async B, fused norms + top-5
// ---------------------------------------------------------------------------
__global__ __launch_bounds__(256)
void sim_kernel(const float* __restrict__ ev, int N) {
    extern __shared__ __align__(16) unsigned char sm[];
    __shared__ float s_rnorm[TILE_N];

    int tid = threadIdx.x, w = tid >> 5, lane = tid & 31;
    int n0 = blockIdx.x * TILE_N;
    uint32_t smb = smem_u32(sm);

    // A LDG mapping: slot = tid + 256*i -> row = (tid>>4)+16i, col4 = tid&15
    int rbase = tid >> 4, col4 = tid & 15;

    // B cp.async mapping: slot = tid + 256*j -> qrow = slot>>3, c16 = slot&7
    int q0 = tid >> 3, c16 = tid & 7;

    float4 av[8];
    float  nsq[8];
    #pragma unroll
    for (int i = 0; i < 8; i++) nsq[i] = 0.f;
    float acc[8][4];
    #pragma unroll
    for (int t = 0; t < 8; t++)
        #pragma unroll
        for (int j = 0; j < 4; j++) acc[t][j] = 0.f;

    // ldmatrix invariant addresses
    uint32_t aAddrBase = smb + (uint32_t)(16 * w + (lane & 15)) * A_STR
                             + (uint32_t)(lane >> 4) * 16;
    uint32_t bAddrBase = smb + B_BASE
                       + (uint32_t)((lane & 7) + ((lane >> 4) << 3)) * A_STR
                       + (uint32_t)((lane >> 3) & 1) * 16;

    // ---- prologue: chunk 0 ----
    {
        #pragma unroll
        for (int j = 0; j < 2; j++) {
            int qr = q0 + 32 * j;
            cpa16(smb + B_BASE + (uint32_t)qr * A_STR + c16 * 16,
                  (const char*)g_qbf + (size_t)qr * (HID * 2) + c16 * 16);
        }
        CP_COMMIT();
        #pragma unroll
        for (int i = 0; i < 8; i++) {
            int r = rbase + 16 * i;
            av[i] = make_float4(0.f, 0.f, 0.f, 0.f);
            if (n0 + r < N)
                av[i] = *(const float4*)&ev[(size_t)(n0 + r) * HID + col4 * 4];
        }
        unsigned char* Ab = sm;
        #pragma unroll
        for (int i = 0; i < 8; i++) {
            float4 v = av[i];
            nsq[i] += v.x * v.x + v.y * v.y + v.z * v.z + v.w * v.w;
            *(uint2*)(Ab + (rbase + 16 * i) * A_STR + col4 * 8) = cvt4_bf16(v);
        }
        CP_WAIT0();
    }
    __syncthreads();

    // ---- main loop ----
    for (int c = 0; c < NCH; ++c) {
        int buf = c & 1, nxt = buf ^ 1;
        bool more = (c + 1 < NCH);
        if (more) {
            int k0 = (c + 1) * CHK;
            #pragma unroll
            for (int j = 0; j < 2; j++) {
                int qr = q0 + 32 * j;
                cpa16(smb + B_BASE + (uint32_t)nxt * B_BUF + (uint32_t)qr * A_STR + c16 * 16,
                      (const char*)g_qbf + (size_t)qr * (HID * 2) + k0 * 2 + c16 * 16);
            }
            CP_COMMIT();
            #pragma unroll
            for (int i = 0; i < 8; i++) {
                int r = rbase + 16 * i;
                av[i] = make_float4(0.f, 0.f, 0.f, 0.f);
                if (n0 + r < N)
                    av[i] = *(const float4*)&ev[(size_t)(n0 + r) * HID + k0 + col4 * 4];
            }
        }

        // compute current buffer: 4 k16 steps, 4 n-tile pairs
        {
            uint32_t ab = aAddrBase + (uint32_t)buf * A_BUF;
            uint32_t bb = bAddrBase + (uint32_t)buf * B_BUF;
            #pragma unroll
            for (int s = 0; s < 4; s++) {
                uint32_t af[4];
                ldsm_x4(ab + s * 32, af);
                #pragma unroll
                for (int tp = 0; tp < 4; tp++) {
                    uint32_t bf[4];
                    ldsm_x4(bb + (uint32_t)tp * (16 * A_STR) + s * 32, bf);
                    mma_bf16(acc[2 * tp],     af, bf);
                    mma_bf16(acc[2 * tp + 1], af, bf + 2);
                }
            }
        }

        if (more) {
            unsigned char* Ab = sm + nxt * A_BUF;
            #pragma unroll
            for (int i = 0; i < 8; i++) {
                float4 v = av[i];
                nsq[i] += v.x * v.x + v.y * v.y + v.z * v.z + v.w * v.w;
                *(uint2*)(Ab + (rbase + 16 * i) * A_STR + col4 * 8) = cvt4_bf16(v);
            }
        }
        CP_WAIT0();
        __syncthreads();
    }

    // ---- evidence norms: reduce across the 16 threads sharing each row ----
    #pragma unroll
    for (int i = 0; i < 8; i++) {
        float v = nsq[i];
        v += __shfl_xor_sync(0xffffffffu, v, 1, 16);
        v += __shfl_xor_sync(0xffffffffu, v, 2, 16);
        v += __shfl_xor_sync(0xffffffffu, v, 4, 16);
        v += __shfl_xor_sync(0xffffffffu, v, 8, 16);
        if ((tid & 15) == 0)
            s_rnorm[rbase + 16 * i] = 1.f / fmaxf(sqrtf(v), 1e-12f);
    }
    __syncthreads();

    // ---- stage scores Ds[q][m] (smem union) ----
    float* Ds = (float*)sm;
    int mlo = 16 * w + (lane >> 2), mhi = mlo + 8;
    float rlo = s_rnorm[mlo], rhi = s_rnorm[mhi];
    bool vlo = (n0 + mlo) < N, vhi = (n0 + mhi) < N;
    #pragma unroll
    for (int t = 0; t < 8; t++) {
        int n = 8 * t + 2 * (lane & 3);
        Ds[n * DSTR + mlo]       = vlo ? acc[t][0] * rlo : -FLT_MAX;
        Ds[(n + 1) * DSTR + mlo] = vlo ? acc[t][1] * rlo : -FLT_MAX;
        Ds[n * DSTR + mhi]       = vhi ? acc[t][2] * rhi : -FLT_MAX;
        Ds[(n + 1) * DSTR + mhi] = vhi ? acc[t][3] * rhi : -FLT_MAX;
    }
    __syncthreads();

    // ---- per-block approx top-5: warp w owns queries 8w..8w+7 ----
    for (int j = 0; j < 8; j++) {
        int q = w * 8 + j;
        float c0 = Ds[q * DSTR + lane];
        float c1 = Ds[q * DSTR + lane + 32];
        float c2 = Ds[q * DSTR + lane + 64];
        float c3 = Ds[q * DSTR + lane + 96];
        int i0 = lane, i1 = lane + 32, i2 = lane + 64, i3 = lane + 96;
        #pragma unroll
        for (int t = 0; t < KTOP; t++) {
            float bs = c0; int bi = i0;
            if (c1 > bs || (c1 == bs && i1 < bi)) { bs = c1; bi = i1; }
            if (c2 > bs || (c2 == bs && i2 < bi)) { bs = c2; bi = i2; }
            if (c3 > bs || (c3 == bs && i3 < bi)) { bs = c3; bi = i3; }
            #pragma unroll
            for (int o = 16; o; o >>= 1) {
                float os = __shfl_xor_sync(0xffffffffu, bs, o);
                int   oi = __shfl_xor_sync(0xffffffffu, bi, o);
                if (os > bs || (os == bs && oi < bi)) { bs = os; bi = oi; }
            }
            if (lane == 0) {
                size_t p = ((size_t)q * gridDim.x + blockIdx.x) * KTOP + t;
                g_pscore[p] = bs;
                g_pidx[p]   = n0 + bi;
            }
            if      (i0 == bi) c0 = -FLT_MAX;
            else if (i1 == bi) c1 = -FLT_MAX;
            else if (i2 == bi) c2 = -FLT_MAX;
            else if (i3 == bi) c3 = -FLT_MAX;
        }
    }
}

// ---------------------------------------------------------------------------
// K3: merge per-block partials -> global top-16 candidates per query
// ---------------------------------------------------------------------------
__device__ __forceinline__ void ins16(float* s, int* id, float sc, int ix) {
    if (!(sc > s[NCAND-1] || (sc == s[NCAND-1] && ix < id[NCAND-1]))) return;
    int j = NCAND - 1;
    while (j > 0 && (sc > s[j-1] || (sc == s[j-1] && ix < id[j-1]))) {
        s[j] = s[j-1]; id[j] = id[j-1]; --j;
    }
    s[j] = sc; id[j] = ix;
}

__global__ void merge_kernel(int nblk) {
    __shared__ float ss[256 * NCAND];
    __shared__ int   si[256 * NCAND];
    int q = blockIdx.x, tid = threadIdx.x;
    int M = nblk * KTOP;

    float s[NCAND]; int id[NCAND];
    #pragma unroll
    for (int j = 0; j < NCAND; j++) { s[j] = -FLT_MAX; id[j] = 0x7fffffff; }
    size_t bse = (size_t)q * nblk * KTOP;
    for (int c = tid; c < M; c += 256)
        ins16(s, id, g_pscore[bse + c], g_pidx[bse + c]);
    #pragma unroll
    for (int j = 0; j < NCAND; j++) { ss[tid*NCAND+j] = s[j]; si[tid*NCAND+j] = id[j]; }
    __syncthreads();

    if (tid < 32) {
        float s2[NCAND]; int i2[NCAND];
        #pragma unroll
        for (int j = 0; j < NCAND; j++) { s2[j] = -FLT_MAX; i2[j] = 0x7fffffff; }
        for (int c = tid; c < 256 * NCAND; c += 32) ins16(s2, i2, ss[c], si[c]);
        __syncwarp();
        #pragma unroll
        for (int j = 0; j < NCAND; j++) { ss[tid*NCAND+j] = s2[j]; si[tid*NCAND+j] = i2[j]; }
        __syncwarp();
        if (tid == 0) {
            float s3[NCAND]; int i3[NCAND];
            #pragma unroll
            for (int j = 0; j < NCAND; j++) { s3[j] = -FLT_MAX; i3[j] = 0x7fffffff; }
            for (int c = 0; c < 32 * NCAND; c++) ins16(s3, i3, ss[c], si[c]);
            #pragma unroll
            for (int j = 0; j < NCAND; j++) g_cand[q * NCAND + j] = i3[j];
        }
    }
}

// ---------------------------------------------------------------------------
// K4: exact fp32 rescore of 16 candidates per query -> final top-5
// ---------------------------------------------------------------------------
__global__ void rescore_kernel(const float* __restrict__ ev,
                               float* __restrict__ out, int out_size) {
    __shared__ float cs[NCAND];
    int q = blockIdx.x, tid = threadIdx.x;
    int w = tid >> 5, lane = tid & 31;

    for (int t = 0; t < 4; t++) {
        int c = w * 4 + t;
        int idx = g_cand[q * NCAND + c];
        const float* e = &ev[(size_t)idx * HID];
        const float* qv = &g_qn[q * HID];
        float dot = 0.f, ssq = 0.f;
        #pragma unroll
        for (int kk = 0; kk < HID / 32; kk++) {
            float x = e[lane + kk * 32];
            dot += x * qv[lane + kk * 32];
            ssq += x * x;
        }
        #pragma unroll
        for (int o = 16; o; o >>= 1) {
            dot += __shfl_xor_sync(0xffffffffu, dot, o);
            ssq += __shfl_xor_sync(0xffffffffu, ssq, o);
        }
        if (lane == 0) cs[c] = dot / fmaxf(sqrtf(ssq), 1e-12f);
    }
    __syncthreads();

    if (w == 0) {
        float sc = (lane < NCAND) ? cs[lane] : -FLT_MAX;
        int   ix = (lane < NCAND) ? g_cand[q * NCAND + lane] : 0x7fffffff;
        #pragma unroll
        for (int t = 0; t < KTOP; t++) {
            float bs = sc; int bi = ix;
            #pragma unroll
            for (int o = 16; o; o >>= 1) {
                float os = __shfl_xor_sync(0xffffffffu, bs, o);
                int   oi = __shfl_xor_sync(0xffffffffu, bi, o);
                if (os > bs || (os == bs && oi < bi)) { bs = os; bi = oi; }
            }
            if (lane == 0) {
                int pi = q * KTOP + t;
                int ps = BQ * KTOP + q * KTOP + t;
                if (pi < out_size) out[pi] = (float)bi;
                if (ps < out_size) out[ps] = bs;
            }
            if (ix == bi) sc = -FLT_MAX;   // winner pops (indices unique)
        }
    }
}

// ---------------------------------------------------------------------------
extern "C" void kernel_launch(void* const* d_in, const int* in_sizes, int n_in,
                              void* d_out, int out_size) {
    (void)n_in;
    const float* qe = (const float*)d_in[0];
    const float* ev = (const float*)d_in[1];
    float* out = (float*)d_out;

    int N = in_sizes[1] / HID;
    int nblk = (N + TILE_N - 1) / TILE_N;
    if (nblk > NBLK_MAX) nblk = NBLK_MAX;

    cudaFuncSetAttribute(sim_kernel, cudaFuncAttributeMaxDynamicSharedMemorySize, DYN_SMEM);

    qnorm_kernel<<<BQ, 256>>>(qe);
    sim_kernel<<<nblk, 256, DYN_SMEM>>>(ev, N);
    merge_kernel<<<BQ, 256>>>(nblk);
    rescore_kernel<<<BQ, 128>>>(ev, out, out_size);
}